// round 1
// baseline (speedup 1.0000x reference)
#include <cuda_runtime.h>
#include <math.h>

#define SEQ  8192
#define DIN  512
#define DOUT 64

// (1/sqrt(64)) * log2(e) — folded into Q at smem-load time so softmax can use exp2f.
#define SCALE2 0.18033688011112042f

// Scratch (allocation-free rule: __device__ globals)
__device__ float g_Q[SEQ * DOUT];
__device__ float g_K[SEQ * DOUT];
__device__ float g_V[SEQ * DOUT];

// ---------------------------------------------------------------------------
// Kernel 1: QKV projection. grid = (SEQ/64, 3), block = 256.
// Each block: 64 rows x 64 cols, K-chunks of 32. Thread tile 4x4.
// ---------------------------------------------------------------------------
__global__ __launch_bounds__(256, 1)
void qkv_kernel(const float* __restrict__ x,
                const float* __restrict__ wq,
                const float* __restrict__ wk,
                const float* __restrict__ wv)
{
    const int mat  = blockIdx.y;
    const float* W = (mat == 0) ? wq : (mat == 1) ? wk : wv;
    float* out     = (mat == 0) ? g_Q : (mat == 1) ? g_K : g_V;
    const int row0 = blockIdx.x * 64;

    __shared__ float xs[64 * 40];   // 64 rows, stride 40 (pad, 16B-aligned rows)
    __shared__ float ws[32 * 64];   // k-major, natural

    const int tid = threadIdx.x;
    const int ty  = tid >> 4;       // 0..15 -> rows ty + 16*m
    const int tx  = tid & 15;       // 0..15 -> cols 4*tx .. 4*tx+3

    float acc[4][4] = {};

    for (int kc = 0; kc < DIN; kc += 32) {
        // load x tile: 64 x 32
        #pragma unroll
        for (int it = 0; it < 2; ++it) {
            int f = it * 256 + tid;
            int r = f >> 3, kg = f & 7;
            float4 v = *(const float4*)&x[(row0 + r) * DIN + kc + kg * 4];
            *(float4*)&xs[r * 40 + kg * 4] = v;
        }
        // load W tile: 32 x 64
        #pragma unroll
        for (int it = 0; it < 2; ++it) {
            int f = it * 256 + tid;
            int k = f >> 4, dg = f & 15;
            float4 v = *(const float4*)&W[(kc + k) * DOUT + dg * 4];
            *(float4*)&ws[k * 64 + dg * 4] = v;
        }
        __syncthreads();

        #pragma unroll 8
        for (int k = 0; k < 32; ++k) {
            float4 b = *(float4*)&ws[k * 64 + tx * 4];
            #pragma unroll
            for (int m = 0; m < 4; ++m) {
                float a = xs[(ty + 16 * m) * 40 + k];
                acc[m][0] += a * b.x;
                acc[m][1] += a * b.y;
                acc[m][2] += a * b.z;
                acc[m][3] += a * b.w;
            }
        }
        __syncthreads();
    }

    #pragma unroll
    for (int m = 0; m < 4; ++m) {
        float4 v = make_float4(acc[m][0], acc[m][1], acc[m][2], acc[m][3]);
        *(float4*)&out[(row0 + ty + 16 * m) * DOUT + tx * 4] = v;
    }
}

// ---------------------------------------------------------------------------
// Kernel 2: fused flash attention. grid = SEQ/64 = 128 blocks, block = 256.
// Br = Bc = 64, d = 64. XOR-swizzled smem (granule = row*16 + (col16 ^ (row&15)))
// gives conflict-free LDS.128 for both GEMMs.
// Thread map (S-GEMM): rows r = ty + 16*i, key-cols c = tx + 16*j.
// Thread map (O):      rows r = ty + 16*i, d-cols  d = 4*tx + j.
// ---------------------------------------------------------------------------
__global__ __launch_bounds__(256, 1)
void flash_kernel(float* __restrict__ out)
{
    __shared__ float Qs[64 * 64];
    __shared__ float Ks[64 * 64];   // reused as P-staging between GEMMs
    __shared__ float Vs[64 * 64];

    float4* Qg = (float4*)Qs;
    float4* Kg = (float4*)Ks;
    float4* Vg = (float4*)Vs;

    const int tid   = threadIdx.x;
    const int ty    = tid >> 4;     // 0..15
    const int tx    = tid & 15;     // 0..15
    const int qrow0 = blockIdx.x * 64;

    // Load Q tile: prescale by SCALE2, store swizzled.
    #pragma unroll
    for (int it = 0; it < 4; ++it) {
        int f = it * 256 + tid;
        int r = f >> 4, kg = f & 15;
        float4 v = *(const float4*)&g_Q[(qrow0 + r) * DOUT + kg * 4];
        v.x *= SCALE2; v.y *= SCALE2; v.z *= SCALE2; v.w *= SCALE2;
        Qg[r * 16 + (kg ^ (r & 15))] = v;
    }

    float mrow[4], lrow[4], O[4][4];
    #pragma unroll
    for (int i = 0; i < 4; ++i) {
        mrow[i] = -INFINITY;
        lrow[i] = 0.f;
        O[i][0] = O[i][1] = O[i][2] = O[i][3] = 0.f;
    }
    __syncthreads();

    for (int t = 0; t < SEQ / 64; ++t) {
        // Load K, V tiles (swizzled)
        #pragma unroll
        for (int it = 0; it < 4; ++it) {
            int f = it * 256 + tid;
            int r = f >> 4, kg = f & 15;
            int g = r * 16 + (kg ^ (r & 15));
            Kg[g] = *(const float4*)&g_K[(t * 64 + r) * DOUT + kg * 4];
            Vg[g] = *(const float4*)&g_V[(t * 64 + r) * DOUT + kg * 4];
        }
        __syncthreads();

        // ---- S = Q K^T  (scaled; 4x4 per thread) ----
        float s[4][4] = {};
        #pragma unroll 4
        for (int kg = 0; kg < 16; ++kg) {
            float4 qf[4], kf[4];
            #pragma unroll
            for (int i = 0; i < 4; ++i) {
                qf[i] = Qg[(ty + 16 * i) * 16 + (kg ^ ty)];
                kf[i] = Kg[(tx + 16 * i) * 16 + (kg ^ tx)];
            }
            #pragma unroll
            for (int i = 0; i < 4; ++i)
                #pragma unroll
                for (int j = 0; j < 4; ++j) {
                    s[i][j] += qf[i].x * kf[j].x;
                    s[i][j] += qf[i].y * kf[j].y;
                    s[i][j] += qf[i].z * kf[j].z;
                    s[i][j] += qf[i].w * kf[j].w;
                }
        }

        // ---- online softmax (rows split across 16 tx lanes) ----
        #pragma unroll
        for (int i = 0; i < 4; ++i) {
            float rm = fmaxf(fmaxf(s[i][0], s[i][1]), fmaxf(s[i][2], s[i][3]));
            #pragma unroll
            for (int d = 1; d < 16; d <<= 1)
                rm = fmaxf(rm, __shfl_xor_sync(0xffffffffu, rm, d));
            float mn   = fmaxf(mrow[i], rm);
            float corr = exp2f(mrow[i] - mn);
            mrow[i]    = mn;
            float ps = 0.f;
            #pragma unroll
            for (int j = 0; j < 4; ++j) {
                float p = exp2f(s[i][j] - mn);
                s[i][j] = p;
                ps += p;
            }
            #pragma unroll
            for (int d = 1; d < 16; d <<= 1)
                ps += __shfl_xor_sync(0xffffffffu, ps, d);
            lrow[i] = lrow[i] * corr + ps;
            O[i][0] *= corr; O[i][1] *= corr; O[i][2] *= corr; O[i][3] *= corr;
        }

        __syncthreads();   // everyone done reading Ks

        // ---- stage P into Ks buffer: Ps[r][c], swizzled (scalar stores) ----
        #pragma unroll
        for (int i = 0; i < 4; ++i)
            #pragma unroll
            for (int j = 0; j < 4; ++j) {
                int r = ty + 16 * i;
                int c = tx + 16 * j;
                Ks[((r * 16 + ((c >> 2) ^ ty)) << 2) + (c & 3)] = s[i][j];
            }
        __syncthreads();

        // ---- O += P @ V  (A scalar-broadcast, B vectorized) ----
        #pragma unroll 4
        for (int c = 0; c < 64; ++c) {
            float4 b = Vg[c * 16 + (tx ^ (c & 15))];
            #pragma unroll
            for (int i = 0; i < 4; ++i) {
                float a = Ks[(((ty + 16 * i) * 16 + ((c >> 2) ^ ty)) << 2) + (c & 3)];
                O[i][0] += a * b.x;
                O[i][1] += a * b.y;
                O[i][2] += a * b.z;
                O[i][3] += a * b.w;
            }
        }
        __syncthreads();   // before next tile's K/V overwrite
    }

    // ---- epilogue: normalize and store ----
    #pragma unroll
    for (int i = 0; i < 4; ++i) {
        float inv = 1.0f / lrow[i];
        float4 v = make_float4(O[i][0] * inv, O[i][1] * inv,
                               O[i][2] * inv, O[i][3] * inv);
        *(float4*)&out[(qrow0 + ty + 16 * i) * DOUT + tx * 4] = v;
    }
}

// ---------------------------------------------------------------------------
extern "C" void kernel_launch(void* const* d_in, const int* in_sizes, int n_in,
                              void* d_out, int out_size)
{
    (void)in_sizes; (void)n_in; (void)out_size;
    const float* x  = (const float*)d_in[0];
    const float* wq = (const float*)d_in[1];
    const float* wk = (const float*)d_in[2];
    const float* wv = (const float*)d_in[3];
    float* out      = (float*)d_out;

    qkv_kernel<<<dim3(SEQ / 64, 3), 256>>>(x, wq, wk, wv);
    flash_kernel<<<SEQ / 64, 256>>>(out);
}

// round 3
// speedup vs baseline: 1.6276x; 1.6276x over previous
#include <cuda_runtime.h>
#include <math.h>
#include <stdint.h>

#define SEQ  8192
#define DIN  512
#define DOUT 64

#define BM 64                  // Q rows per CTA (4 warps x m16)
#define BN 64                  // keys per tile
#define NT (SEQ / BN)          // 128 tiles
#define W  68                  // smem row stride in floats (conflict-free)

// (1/sqrt(64)) * log2(e) folded into Q
#define SCALE2 0.18033688011112042f

// ---------------- scratch ----------------
__device__ float g_Q[SEQ * DOUT];
__device__ float g_K[SEQ * DOUT];
__device__ float g_V[SEQ * DOUT];

// ---------------- helpers ----------------
__device__ __forceinline__ float t32(float x) {          // round to tf32
    uint32_t u;
    asm("cvt.rna.tf32.f32 %0, %1;" : "=r"(u) : "f"(x));
    return __uint_as_float(u);
}
__device__ __forceinline__ float ex2(float x) {
    float r;
    asm("ex2.approx.f32 %0, %1;" : "=f"(r) : "f"(x));
    return r;
}
__device__ __forceinline__ void mma8(float d[4], float a0, float a1, float a2, float a3,
                                     float b0, float b1) {
    asm volatile(
        "mma.sync.aligned.m16n8k8.row.col.f32.tf32.tf32.f32 "
        "{%0,%1,%2,%3}, {%4,%5,%6,%7}, {%8,%9}, {%0,%1,%2,%3};"
        : "+f"(d[0]), "+f"(d[1]), "+f"(d[2]), "+f"(d[3])
        : "r"(__float_as_uint(a0)), "r"(__float_as_uint(a1)),
          "r"(__float_as_uint(a2)), "r"(__float_as_uint(a3)),
          "r"(__float_as_uint(b0)), "r"(__float_as_uint(b1)));
}
__device__ __forceinline__ void cp16(float* dst, const float* src) {
    uint32_t d = (uint32_t)__cvta_generic_to_shared(dst);
    asm volatile("cp.async.cg.shared.global [%0], [%1], 16;" :: "r"(d), "l"(src));
}
#define CP_COMMIT() asm volatile("cp.async.commit_group;" ::: "memory")
#define CP_WAIT(n)  asm volatile("cp.async.wait_group %0;" :: "n"(n) : "memory")

// ---------------------------------------------------------------------------
// Kernel 1: QKV projection (fp32 SIMT). grid=(SEQ/64,3), block=256.
// ---------------------------------------------------------------------------
__global__ __launch_bounds__(256, 1)
void qkv_kernel(const float* __restrict__ x,
                const float* __restrict__ wq,
                const float* __restrict__ wk,
                const float* __restrict__ wv)
{
    const int mat  = blockIdx.y;
    const float* Wm = (mat == 0) ? wq : (mat == 1) ? wk : wv;
    float* out      = (mat == 0) ? g_Q : (mat == 1) ? g_K : g_V;
    const int row0 = blockIdx.x * 64;

    __shared__ float xs[64 * 40];
    __shared__ float ws[32 * 64];

    const int tid = threadIdx.x;
    const int ty  = tid >> 4;
    const int tx  = tid & 15;

    float acc[4][4] = {};

    for (int kc = 0; kc < DIN; kc += 32) {
        #pragma unroll
        for (int it = 0; it < 2; ++it) {
            int f = it * 256 + tid;
            int r = f >> 3, kg = f & 7;
            *(float4*)&xs[r * 40 + kg * 4] = *(const float4*)&x[(row0 + r) * DIN + kc + kg * 4];
        }
        #pragma unroll
        for (int it = 0; it < 2; ++it) {
            int f = it * 256 + tid;
            int k = f >> 4, dg = f & 15;
            *(float4*)&ws[k * 64 + dg * 4] = *(const float4*)&Wm[(kc + k) * DOUT + dg * 4];
        }
        __syncthreads();
        #pragma unroll 8
        for (int k = 0; k < 32; ++k) {
            float4 b = *(float4*)&ws[k * 64 + tx * 4];
            #pragma unroll
            for (int m = 0; m < 4; ++m) {
                float a = xs[(ty + 16 * m) * 40 + k];
                acc[m][0] += a * b.x; acc[m][1] += a * b.y;
                acc[m][2] += a * b.z; acc[m][3] += a * b.w;
            }
        }
        __syncthreads();
    }

    #pragma unroll
    for (int m = 0; m < 4; ++m) {
        float4 v = make_float4(acc[m][0], acc[m][1], acc[m][2], acc[m][3]);
        *(float4*)&out[(row0 + ty + 16 * m) * DOUT + tx * 4] = v;
    }
}

// ---------------------------------------------------------------------------
// Kernel 2: flash attention via mma.sync tf32. grid=SEQ/BM=128, block=128.
// smem: Qs | K0 | K1 | V0 | V1, each 64 rows x W floats.
// ---------------------------------------------------------------------------
__device__ __forceinline__ void load_tile(float* ks, float* vs, int t, int tid) {
    const float* kg = g_K + (size_t)t * BN * DOUT;
    const float* vg = g_V + (size_t)t * BN * DOUT;
    #pragma unroll
    for (int i = 0; i < 8; ++i) {
        int idx = i * 128 + tid;          // 0..1023
        int r = idx >> 4, c4 = idx & 15;
        cp16(&ks[r * W + c4 * 4], &kg[r * DOUT + c4 * 4]);
        cp16(&vs[r * W + c4 * 4], &vg[r * DOUT + c4 * 4]);
    }
}

__global__ __launch_bounds__(128, 1)
void flash_kernel(float* __restrict__ out)
{
    extern __shared__ float sm[];
    float* Qs = sm;
    float* K0 = sm + 64 * W;
    float* K1 = sm + 2 * 64 * W;
    float* V0 = sm + 3 * 64 * W;
    float* V1 = sm + 4 * 64 * W;

    const int tid  = threadIdx.x;
    const int lane = tid & 31;
    const int wid  = tid >> 5;
    const int qrow0 = blockIdx.x * BM;
    const int lq = lane >> 2;     // 0..7 (group)
    const int lr = lane & 3;      // 0..3 (thread in group)

    // prefetch tile 0
    load_tile(K0, V0, 0, tid);
    CP_COMMIT();

    // stage Q tile (raw fp32)
    for (int i = tid; i < 64 * 16; i += 128) {
        int r = i >> 4, c4 = i & 15;
        *(float4*)&Qs[r * W + c4 * 4] = *(const float4*)&g_Q[(qrow0 + r) * DOUT + c4 * 4];
    }
    __syncthreads();

    // build Q fragments (hi/lo tf32 split), prescaled
    float qh[8][4], ql[8][4];
    {
        const int r0 = wid * 16 + lq;
        #pragma unroll
        for (int kc = 0; kc < 8; ++kc) {
            #pragma unroll
            for (int j = 0; j < 4; ++j) {
                int rr = r0 + (j & 1) * 8;
                int cc = lr + (j >> 1) * 4;
                float q = Qs[rr * W + kc * 8 + cc] * SCALE2;
                float h = t32(q);
                qh[kc][j] = h;
                ql[kc][j] = t32(q - h);
            }
        }
    }

    float m0 = -INFINITY, m1 = -INFINITY, l0 = 0.f, l1 = 0.f;
    float o[8][4];
    #pragma unroll
    for (int i = 0; i < 8; ++i)
        o[i][0] = o[i][1] = o[i][2] = o[i][3] = 0.f;

    #pragma unroll 1
    for (int t = 0; t < NT; ++t) {
        float* ks = (t & 1) ? K1 : K0;
        float* vs = (t & 1) ? V1 : V0;

        if (t + 1 < NT) {
            load_tile((t & 1) ? K0 : K1, (t & 1) ? V0 : V1, t + 1, tid);
            CP_COMMIT();
            CP_WAIT(1);
        } else {
            CP_WAIT(0);
        }
        __syncthreads();

        // ---- S = Q K^T, 3-pass tf32 ----
        float s[8][4];
        #pragma unroll
        for (int nt = 0; nt < 8; ++nt) {
            s[nt][0] = s[nt][1] = s[nt][2] = s[nt][3] = 0.f;
            #pragma unroll
            for (int kc = 0; kc < 8; ++kc) {
                float b0 = ks[(nt * 8 + lq) * W + kc * 8 + lr];
                float b1 = ks[(nt * 8 + lq) * W + kc * 8 + lr + 4];
                float bh0 = t32(b0), bl0 = t32(b0 - bh0);
                float bh1 = t32(b1), bl1 = t32(b1 - bh1);
                mma8(s[nt], qh[kc][0], qh[kc][1], qh[kc][2], qh[kc][3], bh0, bh1);
                mma8(s[nt], ql[kc][0], ql[kc][1], ql[kc][2], ql[kc][3], bh0, bh1);
                mma8(s[nt], qh[kc][0], qh[kc][1], qh[kc][2], qh[kc][3], bl0, bl1);
            }
        }

        // ---- online softmax (rows r0 = slots 0,1 ; r1 = slots 2,3) ----
        float mx0 = -INFINITY, mx1 = -INFINITY;
        #pragma unroll
        for (int nt = 0; nt < 8; ++nt) {
            mx0 = fmaxf(mx0, fmaxf(s[nt][0], s[nt][1]));
            mx1 = fmaxf(mx1, fmaxf(s[nt][2], s[nt][3]));
        }
        mx0 = fmaxf(mx0, __shfl_xor_sync(0xffffffffu, mx0, 1));
        mx0 = fmaxf(mx0, __shfl_xor_sync(0xffffffffu, mx0, 2));
        mx1 = fmaxf(mx1, __shfl_xor_sync(0xffffffffu, mx1, 1));
        mx1 = fmaxf(mx1, __shfl_xor_sync(0xffffffffu, mx1, 2));

        float nm0 = fmaxf(m0, mx0), nm1 = fmaxf(m1, mx1);
        float cr0 = ex2(m0 - nm0),  cr1 = ex2(m1 - nm1);
        m0 = nm0; m1 = nm1;

        float ps0 = 0.f, ps1 = 0.f;
        #pragma unroll
        for (int nt = 0; nt < 8; ++nt) {
            float p0 = t32(ex2(s[nt][0] - nm0));
            float p1 = t32(ex2(s[nt][1] - nm0));
            float p2 = t32(ex2(s[nt][2] - nm1));
            float p3 = t32(ex2(s[nt][3] - nm1));
            s[nt][0] = p0; s[nt][1] = p1; s[nt][2] = p2; s[nt][3] = p3;
            ps0 += p0 + p1;
            ps1 += p2 + p3;
        }
        ps0 += __shfl_xor_sync(0xffffffffu, ps0, 1);
        ps0 += __shfl_xor_sync(0xffffffffu, ps0, 2);
        ps1 += __shfl_xor_sync(0xffffffffu, ps1, 1);
        ps1 += __shfl_xor_sync(0xffffffffu, ps1, 2);
        l0 = l0 * cr0 + ps0;
        l1 = l1 * cr1 + ps1;

        #pragma unroll
        for (int nt = 0; nt < 8; ++nt) {
            o[nt][0] *= cr0; o[nt][1] *= cr0;
            o[nt][2] *= cr1; o[nt][3] *= cr1;
        }

        // ---- O += P @ V  (P stays in regs; V rows permuted 2m/2m+1) ----
        #pragma unroll
        for (int nd = 0; nd < 8; ++nd) {
            #pragma unroll
            for (int kc = 0; kc < 8; ++kc) {
                float b0 = t32(vs[(kc * 8 + 2 * lr)     * W + nd * 8 + lq]);
                float b1 = t32(vs[(kc * 8 + 2 * lr + 1) * W + nd * 8 + lq]);
                // A-frag order: (r0,c)=slot2c, (r1,c), (r0,c+4)=slot2c+1, (r1,c+4)
                mma8(o[nd], s[kc][0], s[kc][2], s[kc][1], s[kc][3], b0, b1);
            }
        }
        __syncthreads();
    }

    // ---- epilogue ----
    float il0 = 1.0f / l0, il1 = 1.0f / l1;
    int row = qrow0 + wid * 16 + lq;
    #pragma unroll
    for (int nd = 0; nd < 8; ++nd) {
        float2 v0 = make_float2(o[nd][0] * il0, o[nd][1] * il0);
        float2 v1 = make_float2(o[nd][2] * il1, o[nd][3] * il1);
        *(float2*)&out[row * DOUT + nd * 8 + 2 * lr]       = v0;
        *(float2*)&out[(row + 8) * DOUT + nd * 8 + 2 * lr] = v1;
    }
}

// ---------------------------------------------------------------------------
extern "C" void kernel_launch(void* const* d_in, const int* in_sizes, int n_in,
                              void* d_out, int out_size)
{
    (void)in_sizes; (void)n_in; (void)out_size;
    const float* x  = (const float*)d_in[0];
    const float* wq = (const float*)d_in[1];
    const float* wk = (const float*)d_in[2];
    const float* wv = (const float*)d_in[3];
    float* out      = (float*)d_out;

    const int smem_bytes = 5 * 64 * W * sizeof(float);   // 87040
    cudaFuncSetAttribute(flash_kernel, cudaFuncAttributeMaxDynamicSharedMemorySize, smem_bytes);

    qkv_kernel<<<dim3(SEQ / 64, 3), 256>>>(x, wq, wk, wv);
    flash_kernel<<<SEQ / BM, 128, smem_bytes>>>(out);
}

// round 4
// speedup vs baseline: 1.9803x; 1.2167x over previous
#include <cuda_runtime.h>
#include <math.h>
#include <stdint.h>

#define SEQ  8192
#define DIN  512
#define DOUT 64

#define BM 64                  // Q rows per CTA
#define BN 64                  // keys per tile
#define NT (SEQ / BN)          // 128 tiles
#define W  68                  // smem row stride in floats (conflict-free)
#define TSZ (64 * W)           // floats per tile buffer

// (1/sqrt(64)) * log2(e) folded into Q
#define SCALE2 0.18033688011112042f

// ---------------- scratch ----------------
__device__ float g_Q[SEQ * DOUT];
__device__ float g_Kh[SEQ * DOUT];   // tf32 hi part of K
__device__ float g_Kl[SEQ * DOUT];   // tf32 lo part of K
__device__ float g_Vr[SEQ * DOUT];   // tf32-rounded V

// ---------------- helpers ----------------
__device__ __forceinline__ float t32(float x) {          // round to tf32 (RNA)
    uint32_t u;
    asm("cvt.rna.tf32.f32 %0, %1;" : "=r"(u) : "f"(x));
    return __uint_as_float(u);
}
__device__ __forceinline__ float ex2(float x) {
    float r;
    asm("ex2.approx.f32 %0, %1;" : "=f"(r) : "f"(x));
    return r;
}
__device__ __forceinline__ void mma8(float d[4], float a0, float a1, float a2, float a3,
                                     float b0, float b1) {
    asm volatile(
        "mma.sync.aligned.m16n8k8.row.col.f32.tf32.tf32.f32 "
        "{%0,%1,%2,%3}, {%4,%5,%6,%7}, {%8,%9}, {%0,%1,%2,%3};"
        : "+f"(d[0]), "+f"(d[1]), "+f"(d[2]), "+f"(d[3])
        : "r"(__float_as_uint(a0)), "r"(__float_as_uint(a1)),
          "r"(__float_as_uint(a2)), "r"(__float_as_uint(a3)),
          "r"(__float_as_uint(b0)), "r"(__float_as_uint(b1)));
}
__device__ __forceinline__ void cp16(float* dst, const float* src) {
    uint32_t d = (uint32_t)__cvta_generic_to_shared(dst);
    asm volatile("cp.async.cg.shared.global [%0], [%1], 16;" :: "r"(d), "l"(src));
}
#define CP_COMMIT() asm volatile("cp.async.commit_group;" ::: "memory")
#define CP_WAIT(n)  asm volatile("cp.async.wait_group %0;" :: "n"(n) : "memory")

// ---------------------------------------------------------------------------
// Kernel 1: QKV projection (fp32 SIMT). grid=(SEQ/64,3), block=256.
// K is written pre-split (tf32 hi/lo); V pre-rounded to tf32.
// ---------------------------------------------------------------------------
__global__ __launch_bounds__(256, 1)
void qkv_kernel(const float* __restrict__ x,
                const float* __restrict__ wq,
                const float* __restrict__ wk,
                const float* __restrict__ wv)
{
    const int mat   = blockIdx.y;
    const float* Wm = (mat == 0) ? wq : (mat == 1) ? wk : wv;
    const int row0  = blockIdx.x * 64;

    __shared__ float xs[64 * 40];
    __shared__ float ws[32 * 64];

    const int tid = threadIdx.x;
    const int ty  = tid >> 4;
    const int tx  = tid & 15;

    float acc[4][4] = {};

    for (int kc = 0; kc < DIN; kc += 32) {
        #pragma unroll
        for (int it = 0; it < 2; ++it) {
            int f = it * 256 + tid;
            int r = f >> 3, kg = f & 7;
            *(float4*)&xs[r * 40 + kg * 4] = *(const float4*)&x[(row0 + r) * DIN + kc + kg * 4];
        }
        #pragma unroll
        for (int it = 0; it < 2; ++it) {
            int f = it * 256 + tid;
            int k = f >> 4, dg = f & 15;
            *(float4*)&ws[k * 64 + dg * 4] = *(const float4*)&Wm[(kc + k) * DOUT + dg * 4];
        }
        __syncthreads();
        #pragma unroll 8
        for (int k = 0; k < 32; ++k) {
            float4 b = *(float4*)&ws[k * 64 + tx * 4];
            #pragma unroll
            for (int m = 0; m < 4; ++m) {
                float a = xs[(ty + 16 * m) * 40 + k];
                acc[m][0] += a * b.x; acc[m][1] += a * b.y;
                acc[m][2] += a * b.z; acc[m][3] += a * b.w;
            }
        }
        __syncthreads();
    }

    if (mat == 0) {
        #pragma unroll
        for (int m = 0; m < 4; ++m) {
            float4 v = make_float4(acc[m][0], acc[m][1], acc[m][2], acc[m][3]);
            *(float4*)&g_Q[(row0 + ty + 16 * m) * DOUT + tx * 4] = v;
        }
    } else if (mat == 1) {
        #pragma unroll
        for (int m = 0; m < 4; ++m) {
            float4 h, l;
            h.x = t32(acc[m][0]); l.x = t32(acc[m][0] - h.x);
            h.y = t32(acc[m][1]); l.y = t32(acc[m][1] - h.y);
            h.z = t32(acc[m][2]); l.z = t32(acc[m][2] - h.z);
            h.w = t32(acc[m][3]); l.w = t32(acc[m][3] - h.w);
            *(float4*)&g_Kh[(row0 + ty + 16 * m) * DOUT + tx * 4] = h;
            *(float4*)&g_Kl[(row0 + ty + 16 * m) * DOUT + tx * 4] = l;
        }
    } else {
        #pragma unroll
        for (int m = 0; m < 4; ++m) {
            float4 v = make_float4(t32(acc[m][0]), t32(acc[m][1]),
                                   t32(acc[m][2]), t32(acc[m][3]));
            *(float4*)&g_Vr[(row0 + ty + 16 * m) * DOUT + tx * 4] = v;
        }
    }
}

// ---------------------------------------------------------------------------
// Kernel 2: flash attention, mma.sync tf32, grid=128, block=256 (8 warps).
// Warp (mrow = wid&3, khalf = wid>>2): rows mrow*16..+15, keys khalf*32..+31.
// smem: Kh0 Kh1 Kl0 Kl1 V0 V1 (each 64xW) | smx[2][64] | ssm[2][64]
// ---------------------------------------------------------------------------
__device__ __forceinline__ void load_tile(float* sm, int t, int b, int tid) {
    float* kh = sm + b * TSZ;
    float* kl = sm + (2 + b) * TSZ;
    float* vv = sm + (4 + b) * TSZ;
    const float* khg = g_Kh + (size_t)t * BN * DOUT;
    const float* klg = g_Kl + (size_t)t * BN * DOUT;
    const float* vg  = g_Vr + (size_t)t * BN * DOUT;
    #pragma unroll
    for (int i = 0; i < 4; ++i) {
        int idx = i * 256 + tid;          // 0..1023
        int r = idx >> 4, c4 = idx & 15;
        cp16(&kh[r * W + c4 * 4], &khg[r * DOUT + c4 * 4]);
        cp16(&kl[r * W + c4 * 4], &klg[r * DOUT + c4 * 4]);
        cp16(&vv[r * W + c4 * 4], &vg[r * DOUT + c4 * 4]);
    }
}

__global__ __launch_bounds__(256, 1)
void flash_kernel(float* __restrict__ out)
{
    extern __shared__ float sm[];
    float* smx = sm + 6 * TSZ;          // partial max exchange [2][64]
    float* ssm = smx + 128;             // partial sum exchange [2][64]

    const int tid   = threadIdx.x;
    const int lane  = tid & 31;
    const int wid   = tid >> 5;
    const int mrow  = wid & 3;
    const int khalf = wid >> 2;
    const int kb    = khalf * 32;
    const int lq    = lane >> 2;        // 0..7
    const int lr    = lane & 3;         // 0..3
    const int qrow0 = blockIdx.x * BM;
    const int r0    = mrow * 16 + lq;

    // prefetch tile 0
    load_tile(sm, 0, 0, tid);
    CP_COMMIT();

    // stage Q through Kh1 buffer (free until tile-1 prefetch)
    {
        float* Qs = sm + TSZ;
        #pragma unroll
        for (int i = 0; i < 4; ++i) {
            int idx = i * 256 + tid;
            int r = idx >> 4, c4 = idx & 15;
            *(float4*)&Qs[r * W + c4 * 4] = *(const float4*)&g_Q[(qrow0 + r) * DOUT + c4 * 4];
        }
    }
    __syncthreads();

    // Q fragments (hi/lo tf32 split), prescaled
    float qh[8][4], ql[8][4];
    {
        const float* Qs = sm + TSZ;
        #pragma unroll
        for (int kc = 0; kc < 8; ++kc) {
            #pragma unroll
            for (int j = 0; j < 4; ++j) {
                int rr = r0 + (j & 1) * 8;
                int cc = lr + (j >> 1) * 4;
                float q = Qs[rr * W + kc * 8 + cc] * SCALE2;
                float h = t32(q);
                qh[kc][j] = h;
                ql[kc][j] = t32(q - h);
            }
        }
    }
    __syncthreads();   // done reading Q staging before tile-1 prefetch reuses it

    float m0 = -INFINITY, m1 = -INFINITY, l0 = 0.f, l1 = 0.f;
    float o[8][4];
    #pragma unroll
    for (int i = 0; i < 8; ++i)
        o[i][0] = o[i][1] = o[i][2] = o[i][3] = 0.f;

    #pragma unroll 1
    for (int t = 0; t < NT; ++t) {
        const int b = t & 1;
        float* kh = sm + b * TSZ;
        float* kl = sm + (2 + b) * TSZ;
        float* vv = sm + (4 + b) * TSZ;

        if (t + 1 < NT) {
            load_tile(sm, t + 1, b ^ 1, tid);
            CP_COMMIT();
            CP_WAIT(1);
        } else {
            CP_WAIT(0);
        }
        __syncthreads();

        // ---- S = Q K^T over this warp's 32 keys, 3-pass tf32 ----
        float s[4][4];
        #pragma unroll
        for (int nt = 0; nt < 4; ++nt) {
            s[nt][0] = s[nt][1] = s[nt][2] = s[nt][3] = 0.f;
            const int krow = kb + nt * 8 + lq;
            #pragma unroll
            for (int kc = 0; kc < 8; ++kc) {
                float h0 = kh[krow * W + kc * 8 + lr];
                float h1 = kh[krow * W + kc * 8 + lr + 4];
                float c0 = kl[krow * W + kc * 8 + lr];
                float c1 = kl[krow * W + kc * 8 + lr + 4];
                mma8(s[nt], qh[kc][0], qh[kc][1], qh[kc][2], qh[kc][3], h0, h1);
                mma8(s[nt], ql[kc][0], ql[kc][1], ql[kc][2], ql[kc][3], h0, h1);
                mma8(s[nt], qh[kc][0], qh[kc][1], qh[kc][2], qh[kc][3], c0, c1);
            }
        }

        // ---- partial row max, exchange with partner half ----
        float mx0 = -INFINITY, mx1 = -INFINITY;
        #pragma unroll
        for (int nt = 0; nt < 4; ++nt) {
            mx0 = fmaxf(mx0, fmaxf(s[nt][0], s[nt][1]));
            mx1 = fmaxf(mx1, fmaxf(s[nt][2], s[nt][3]));
        }
        mx0 = fmaxf(mx0, __shfl_xor_sync(0xffffffffu, mx0, 1));
        mx0 = fmaxf(mx0, __shfl_xor_sync(0xffffffffu, mx0, 2));
        mx1 = fmaxf(mx1, __shfl_xor_sync(0xffffffffu, mx1, 1));
        mx1 = fmaxf(mx1, __shfl_xor_sync(0xffffffffu, mx1, 2));
        if (lr == 0) {
            smx[khalf * 64 + r0]     = mx0;
            smx[khalf * 64 + r0 + 8] = mx1;
        }
        __syncthreads();
        mx0 = fmaxf(mx0, smx[(khalf ^ 1) * 64 + r0]);
        mx1 = fmaxf(mx1, smx[(khalf ^ 1) * 64 + r0 + 8]);

        float nm0 = fmaxf(m0, mx0), nm1 = fmaxf(m1, mx1);
        float cr0 = ex2(m0 - nm0),  cr1 = ex2(m1 - nm1);
        m0 = nm0; m1 = nm1;

        // ---- P = exp2(S - m), partial sums, exchange ----
        float ps0 = 0.f, ps1 = 0.f;
        #pragma unroll
        for (int nt = 0; nt < 4; ++nt) {
            float p0 = t32(ex2(s[nt][0] - nm0));
            float p1 = t32(ex2(s[nt][1] - nm0));
            float p2 = t32(ex2(s[nt][2] - nm1));
            float p3 = t32(ex2(s[nt][3] - nm1));
            s[nt][0] = p0; s[nt][1] = p1; s[nt][2] = p2; s[nt][3] = p3;
            ps0 += p0 + p1;
            ps1 += p2 + p3;
        }
        ps0 += __shfl_xor_sync(0xffffffffu, ps0, 1);
        ps0 += __shfl_xor_sync(0xffffffffu, ps0, 2);
        ps1 += __shfl_xor_sync(0xffffffffu, ps1, 1);
        ps1 += __shfl_xor_sync(0xffffffffu, ps1, 2);
        if (lr == 0) {
            ssm[khalf * 64 + r0]     = ps0;
            ssm[khalf * 64 + r0 + 8] = ps1;
        }
        __syncthreads();
        l0 = l0 * cr0 + ps0 + ssm[(khalf ^ 1) * 64 + r0];
        l1 = l1 * cr1 + ps1 + ssm[(khalf ^ 1) * 64 + r0 + 8];

        #pragma unroll
        for (int nt = 0; nt < 8; ++nt) {
            o[nt][0] *= cr0; o[nt][1] *= cr0;
            o[nt][2] *= cr1; o[nt][3] *= cr1;
        }

        // ---- O_partial += P @ V over this warp's 32 keys ----
        #pragma unroll
        for (int nd = 0; nd < 8; ++nd) {
            #pragma unroll
            for (int kc = 0; kc < 4; ++kc) {
                const float* vp = &vv[(kb + kc * 8 + 2 * lr) * W + nd * 8 + lq];
                float b0 = vp[0];
                float b1 = vp[W];
                mma8(o[nd], s[kc][0], s[kc][2], s[kc][1], s[kc][3], b0, b1);
            }
        }
        __syncthreads();   // protect alt buffers for next prefetch
    }

    // ---- epilogue: merge partner halves (shared l), normalize, store ----
    float il0 = 1.0f / l0, il1 = 1.0f / l1;
    float* Mb = sm + 4 * TSZ;   // reuse V0 region
    if (khalf == 1) {
        #pragma unroll
        for (int nd = 0; nd < 8; ++nd) {
            *(float2*)&Mb[r0 * W + nd * 8 + 2 * lr]       = make_float2(o[nd][0], o[nd][1]);
            *(float2*)&Mb[(r0 + 8) * W + nd * 8 + 2 * lr] = make_float2(o[nd][2], o[nd][3]);
        }
    }
    __syncthreads();
    if (khalf == 0) {
        int row = qrow0 + r0;
        #pragma unroll
        for (int nd = 0; nd < 8; ++nd) {
            float2 p0 = *(float2*)&Mb[r0 * W + nd * 8 + 2 * lr];
            float2 p1 = *(float2*)&Mb[(r0 + 8) * W + nd * 8 + 2 * lr];
            float2 v0 = make_float2((o[nd][0] + p0.x) * il0, (o[nd][1] + p0.y) * il0);
            float2 v1 = make_float2((o[nd][2] + p1.x) * il1, (o[nd][3] + p1.y) * il1);
            *(float2*)&out[row * DOUT + nd * 8 + 2 * lr]       = v0;
            *(float2*)&out[(row + 8) * DOUT + nd * 8 + 2 * lr] = v1;
        }
    }
}

// ---------------------------------------------------------------------------
extern "C" void kernel_launch(void* const* d_in, const int* in_sizes, int n_in,
                              void* d_out, int out_size)
{
    (void)in_sizes; (void)n_in; (void)out_size;
    const float* x  = (const float*)d_in[0];
    const float* wq = (const float*)d_in[1];
    const float* wk = (const float*)d_in[2];
    const float* wv = (const float*)d_in[3];
    float* out      = (float*)d_out;

    const int smem_bytes = (6 * TSZ + 256) * sizeof(float);   // ~105.5 KB
    cudaFuncSetAttribute(flash_kernel, cudaFuncAttributeMaxDynamicSharedMemorySize, smem_bytes);

    qkv_kernel<<<dim3(SEQ / 64, 3), 256>>>(x, wq, wk, wv);
    flash_kernel<<<SEQ / BM, 256, smem_bytes>>>(out);
}

// round 5
// speedup vs baseline: 2.1867x; 1.1043x over previous
#include <cuda_runtime.h>
#include <math.h>
#include <stdint.h>

#define SEQ  8192
#define DIN  512
#define DOUT 64

#define BM 64                  // Q rows per CTA
#define BN 64                  // keys per tile
#define NT (SEQ / BN)          // 128 tiles
#define W  68                  // smem row stride in floats (conflict-free)
#define TSZ (64 * W)           // floats per tile buffer

// (1/sqrt(64)) * log2(e) folded into Q
#define SCALE2 0.18033688011112042f

// ---------------- scratch ----------------
__device__ float g_Q[SEQ * DOUT];
__device__ float g_Kh[SEQ * DOUT];   // tf32 hi part of K
__device__ float g_Kl[SEQ * DOUT];   // tf32 lo part of K
__device__ float g_Vr[SEQ * DOUT];   // tf32-rounded V

// ---------------- helpers ----------------
__device__ __forceinline__ float t32(float x) {          // round to tf32 (RNA)
    uint32_t u;
    asm("cvt.rna.tf32.f32 %0, %1;" : "=r"(u) : "f"(x));
    return __uint_as_float(u);
}
__device__ __forceinline__ float ex2(float x) {
    float r;
    asm("ex2.approx.f32 %0, %1;" : "=f"(r) : "f"(x));
    return r;
}
__device__ __forceinline__ void mma8(float d[4], float a0, float a1, float a2, float a3,
                                     float b0, float b1) {
    asm volatile(
        "mma.sync.aligned.m16n8k8.row.col.f32.tf32.tf32.f32 "
        "{%0,%1,%2,%3}, {%4,%5,%6,%7}, {%8,%9}, {%0,%1,%2,%3};"
        : "+f"(d[0]), "+f"(d[1]), "+f"(d[2]), "+f"(d[3])
        : "r"(__float_as_uint(a0)), "r"(__float_as_uint(a1)),
          "r"(__float_as_uint(a2)), "r"(__float_as_uint(a3)),
          "r"(__float_as_uint(b0)), "r"(__float_as_uint(b1)));
}
__device__ __forceinline__ void cp16(float* dst, const float* src) {
    uint32_t d = (uint32_t)__cvta_generic_to_shared(dst);
    asm volatile("cp.async.cg.shared.global [%0], [%1], 16;" :: "r"(d), "l"(src));
}
#define CP_COMMIT() asm volatile("cp.async.commit_group;" ::: "memory")
#define CP_WAIT(n)  asm volatile("cp.async.wait_group %0;" :: "n"(n) : "memory")

// ---------------------------------------------------------------------------
// Kernel 1: QKV projection (fp32 SIMT). grid=(SEQ/64,3), block=256.
// K is written pre-split (tf32 hi/lo); V pre-rounded to tf32.
// ---------------------------------------------------------------------------
__global__ __launch_bounds__(256, 1)
void qkv_kernel(const float* __restrict__ x,
                const float* __restrict__ wq,
                const float* __restrict__ wk,
                const float* __restrict__ wv)
{
    const int mat   = blockIdx.y;
    const float* Wm = (mat == 0) ? wq : (mat == 1) ? wk : wv;
    const int row0  = blockIdx.x * 64;

    __shared__ float xs[64 * 40];
    __shared__ float ws[32 * 64];

    const int tid = threadIdx.x;
    const int ty  = tid >> 4;
    const int tx  = tid & 15;

    float acc[4][4] = {};

    for (int kc = 0; kc < DIN; kc += 32) {
        #pragma unroll
        for (int it = 0; it < 2; ++it) {
            int f = it * 256 + tid;
            int r = f >> 3, kg = f & 7;
            *(float4*)&xs[r * 40 + kg * 4] = *(const float4*)&x[(row0 + r) * DIN + kc + kg * 4];
        }
        #pragma unroll
        for (int it = 0; it < 2; ++it) {
            int f = it * 256 + tid;
            int k = f >> 4, dg = f & 15;
            *(float4*)&ws[k * 64 + dg * 4] = *(const float4*)&Wm[(kc + k) * DOUT + dg * 4];
        }
        __syncthreads();
        #pragma unroll 8
        for (int k = 0; k < 32; ++k) {
            float4 b = *(float4*)&ws[k * 64 + tx * 4];
            #pragma unroll
            for (int m = 0; m < 4; ++m) {
                float a = xs[(ty + 16 * m) * 40 + k];
                acc[m][0] += a * b.x; acc[m][1] += a * b.y;
                acc[m][2] += a * b.z; acc[m][3] += a * b.w;
            }
        }
        __syncthreads();
    }

    if (mat == 0) {
        #pragma unroll
        for (int m = 0; m < 4; ++m) {
            float4 v = make_float4(acc[m][0], acc[m][1], acc[m][2], acc[m][3]);
            *(float4*)&g_Q[(row0 + ty + 16 * m) * DOUT + tx * 4] = v;
        }
    } else if (mat == 1) {
        #pragma unroll
        for (int m = 0; m < 4; ++m) {
            float4 h, l;
            h.x = t32(acc[m][0]); l.x = t32(acc[m][0] - h.x);
            h.y = t32(acc[m][1]); l.y = t32(acc[m][1] - h.y);
            h.z = t32(acc[m][2]); l.z = t32(acc[m][2] - h.z);
            h.w = t32(acc[m][3]); l.w = t32(acc[m][3] - h.w);
            *(float4*)&g_Kh[(row0 + ty + 16 * m) * DOUT + tx * 4] = h;
            *(float4*)&g_Kl[(row0 + ty + 16 * m) * DOUT + tx * 4] = l;
        }
    } else {
        #pragma unroll
        for (int m = 0; m < 4; ++m) {
            float4 v = make_float4(t32(acc[m][0]), t32(acc[m][1]),
                                   t32(acc[m][2]), t32(acc[m][3]));
            *(float4*)&g_Vr[(row0 + ty + 16 * m) * DOUT + tx * 4] = v;
        }
    }
}

// ---------------------------------------------------------------------------
// Kernel 2: flash attention, mma.sync tf32, grid=128, block=256 (8 warps).
// Warp (mrow = wid&3, khalf = wid>>2): rows mrow*16..+15, keys khalf*32..+31.
// Split-KV: each key-half keeps its own (m,l,O); merged once in epilogue.
// One __syncthreads per tile.
// smem: Kh0 Kh1 Kl0 Kl1 V0 V1 (each 64xW) | mA[64] lA[64]
// ---------------------------------------------------------------------------
__device__ __forceinline__ void load_tile(float* sm, int t, int b, int tid) {
    float* kh = sm + b * TSZ;
    float* kl = sm + (2 + b) * TSZ;
    float* vv = sm + (4 + b) * TSZ;
    const float* khg = g_Kh + (size_t)t * BN * DOUT;
    const float* klg = g_Kl + (size_t)t * BN * DOUT;
    const float* vg  = g_Vr + (size_t)t * BN * DOUT;
    #pragma unroll
    for (int i = 0; i < 4; ++i) {
        int idx = i * 256 + tid;          // 0..1023
        int r = idx >> 4, c4 = idx & 15;
        cp16(&kh[r * W + c4 * 4], &khg[r * DOUT + c4 * 4]);
        cp16(&kl[r * W + c4 * 4], &klg[r * DOUT + c4 * 4]);
        cp16(&vv[r * W + c4 * 4], &vg[r * DOUT + c4 * 4]);
    }
}

__global__ __launch_bounds__(256, 1)
void flash_kernel(float* __restrict__ out)
{
    extern __shared__ float sm[];
    float* mA = sm + 6 * TSZ;           // epilogue m exchange [64]
    float* lA = mA + 64;                // epilogue l exchange [64]

    const int tid   = threadIdx.x;
    const int lane  = tid & 31;
    const int wid   = tid >> 5;
    const int mrow  = wid & 3;
    const int khalf = wid >> 2;
    const int kb    = khalf * 32;
    const int lq    = lane >> 2;        // 0..7
    const int lr    = lane & 3;         // 0..3
    const int qrow0 = blockIdx.x * BM;
    const int r0    = mrow * 16 + lq;

    // prefetch tile 0
    load_tile(sm, 0, 0, tid);
    CP_COMMIT();

    // stage Q through Kh1 buffer (free until tile-1 prefetch)
    {
        float* Qs = sm + TSZ;
        #pragma unroll
        for (int i = 0; i < 4; ++i) {
            int idx = i * 256 + tid;
            int r = idx >> 4, c4 = idx & 15;
            *(float4*)&Qs[r * W + c4 * 4] = *(const float4*)&g_Q[(qrow0 + r) * DOUT + c4 * 4];
        }
    }
    __syncthreads();

    // Q fragments (hi/lo tf32 split), prescaled
    float qh[8][4], ql[8][4];
    {
        const float* Qs = sm + TSZ;
        #pragma unroll
        for (int kc = 0; kc < 8; ++kc) {
            #pragma unroll
            for (int j = 0; j < 4; ++j) {
                int rr = r0 + (j & 1) * 8;
                int cc = lr + (j >> 1) * 4;
                float q = Qs[rr * W + kc * 8 + cc] * SCALE2;
                float h = t32(q);
                qh[kc][j] = h;
                ql[kc][j] = t32(q - h);
            }
        }
    }
    __syncthreads();   // done reading Q staging before tile-1 prefetch reuses it

    float m0 = -INFINITY, m1 = -INFINITY, l0 = 0.f, l1 = 0.f;
    float o[8][4];
    #pragma unroll
    for (int i = 0; i < 8; ++i)
        o[i][0] = o[i][1] = o[i][2] = o[i][3] = 0.f;

    #pragma unroll 1
    for (int t = 0; t < NT; ++t) {
        const int b = t & 1;
        float* kh = sm + b * TSZ;
        float* kl = sm + (2 + b) * TSZ;
        float* vv = sm + (4 + b) * TSZ;

        // tile t data ready + all reads of buffer b^1 (tile t-1) finished
        CP_WAIT(0);
        __syncthreads();

        // prefetch t+1 into the buffer freed by tile t-1
        if (t + 1 < NT) {
            load_tile(sm, t + 1, b ^ 1, tid);
            CP_COMMIT();
        }

        // ---- S = Q K^T over this warp's 32 keys, 3-pass tf32 ----
        float s[4][4];
        #pragma unroll
        for (int nt = 0; nt < 4; ++nt) {
            s[nt][0] = s[nt][1] = s[nt][2] = s[nt][3] = 0.f;
            const int krow = kb + nt * 8 + lq;
            #pragma unroll
            for (int kc = 0; kc < 8; ++kc) {
                float h0 = kh[krow * W + kc * 8 + lr];
                float h1 = kh[krow * W + kc * 8 + lr + 4];
                float c0 = kl[krow * W + kc * 8 + lr];
                float c1 = kl[krow * W + kc * 8 + lr + 4];
                mma8(s[nt], qh[kc][0], qh[kc][1], qh[kc][2], qh[kc][3], h0, h1);
                mma8(s[nt], ql[kc][0], ql[kc][1], ql[kc][2], ql[kc][3], h0, h1);
                mma8(s[nt], qh[kc][0], qh[kc][1], qh[kc][2], qh[kc][3], c0, c1);
            }
        }

        // ---- warp-local online softmax over this half's 32 keys ----
        float mx0 = -INFINITY, mx1 = -INFINITY;
        #pragma unroll
        for (int nt = 0; nt < 4; ++nt) {
            mx0 = fmaxf(mx0, fmaxf(s[nt][0], s[nt][1]));
            mx1 = fmaxf(mx1, fmaxf(s[nt][2], s[nt][3]));
        }
        mx0 = fmaxf(mx0, __shfl_xor_sync(0xffffffffu, mx0, 1));
        mx0 = fmaxf(mx0, __shfl_xor_sync(0xffffffffu, mx0, 2));
        mx1 = fmaxf(mx1, __shfl_xor_sync(0xffffffffu, mx1, 1));
        mx1 = fmaxf(mx1, __shfl_xor_sync(0xffffffffu, mx1, 2));

        float nm0 = fmaxf(m0, mx0), nm1 = fmaxf(m1, mx1);
        float cr0 = ex2(m0 - nm0),  cr1 = ex2(m1 - nm1);
        m0 = nm0; m1 = nm1;

        float ps0 = 0.f, ps1 = 0.f;
        #pragma unroll
        for (int nt = 0; nt < 4; ++nt) {
            float p0 = t32(ex2(s[nt][0] - nm0));
            float p1 = t32(ex2(s[nt][1] - nm0));
            float p2 = t32(ex2(s[nt][2] - nm1));
            float p3 = t32(ex2(s[nt][3] - nm1));
            s[nt][0] = p0; s[nt][1] = p1; s[nt][2] = p2; s[nt][3] = p3;
            ps0 += p0 + p1;
            ps1 += p2 + p3;
        }
        ps0 += __shfl_xor_sync(0xffffffffu, ps0, 1);
        ps0 += __shfl_xor_sync(0xffffffffu, ps0, 2);
        ps1 += __shfl_xor_sync(0xffffffffu, ps1, 1);
        ps1 += __shfl_xor_sync(0xffffffffu, ps1, 2);
        l0 = l0 * cr0 + ps0;
        l1 = l1 * cr1 + ps1;

        #pragma unroll
        for (int nt = 0; nt < 8; ++nt) {
            o[nt][0] *= cr0; o[nt][1] *= cr0;
            o[nt][2] *= cr1; o[nt][3] *= cr1;
        }

        // ---- O_partial += P @ V over this warp's 32 keys ----
        #pragma unroll
        for (int nd = 0; nd < 8; ++nd) {
            #pragma unroll
            for (int kc = 0; kc < 4; ++kc) {
                const float* vp = &vv[(kb + kc * 8 + 2 * lr) * W + nd * 8 + lq];
                float b0 = vp[0];
                float b1 = vp[W];
                mma8(o[nd], s[kc][0], s[kc][2], s[kc][1], s[kc][3], b0, b1);
            }
        }
    }

    // ---- epilogue: merge key-halves (m, l, O), normalize, store ----
    __syncthreads();   // all warps done with tile buffers
    float* Mb = sm + 4 * TSZ;   // reuse V0 region for O exchange
    if (khalf == 1) {
        if (lr == 0) {
            mA[r0]     = m0;  mA[r0 + 8] = m1;
            lA[r0]     = l0;  lA[r0 + 8] = l1;
        }
        #pragma unroll
        for (int nd = 0; nd < 8; ++nd) {
            *(float2*)&Mb[r0 * W + nd * 8 + 2 * lr]       = make_float2(o[nd][0], o[nd][1]);
            *(float2*)&Mb[(r0 + 8) * W + nd * 8 + 2 * lr] = make_float2(o[nd][2], o[nd][3]);
        }
    }
    __syncthreads();
    if (khalf == 0) {
        float mB0 = mA[r0], mB1 = mA[r0 + 8];
        float lB0 = lA[r0], lB1 = lA[r0 + 8];
        float M0 = fmaxf(m0, mB0), M1 = fmaxf(m1, mB1);
        float a0 = ex2(m0 - M0),  bf0 = ex2(mB0 - M0);
        float a1 = ex2(m1 - M1),  bf1 = ex2(mB1 - M1);
        float L0 = l0 * a0 + lB0 * bf0;
        float L1 = l1 * a1 + lB1 * bf1;
        float il0 = 1.0f / L0, il1 = 1.0f / L1;
        int row = qrow0 + r0;
        #pragma unroll
        for (int nd = 0; nd < 8; ++nd) {
            float2 p0 = *(float2*)&Mb[r0 * W + nd * 8 + 2 * lr];
            float2 p1 = *(float2*)&Mb[(r0 + 8) * W + nd * 8 + 2 * lr];
            float2 v0 = make_float2((o[nd][0] * a0 + p0.x * bf0) * il0,
                                    (o[nd][1] * a0 + p0.y * bf0) * il0);
            float2 v1 = make_float2((o[nd][2] * a1 + p1.x * bf1) * il1,
                                    (o[nd][3] * a1 + p1.y * bf1) * il1);
            *(float2*)&out[row * DOUT + nd * 8 + 2 * lr]       = v0;
            *(float2*)&out[(row + 8) * DOUT + nd * 8 + 2 * lr] = v1;
        }
    }
}

// ---------------------------------------------------------------------------
extern "C" void kernel_launch(void* const* d_in, const int* in_sizes, int n_in,
                              void* d_out, int out_size)
{
    (void)in_sizes; (void)n_in; (void)out_size;
    const float* x  = (const float*)d_in[0];
    const float* wq = (const float*)d_in[1];
    const float* wk = (const float*)d_in[2];
    const float* wv = (const float*)d_in[3];
    float* out      = (float*)d_out;

    const int smem_bytes = (6 * TSZ + 128) * sizeof(float);   // ~102.5 KB
    cudaFuncSetAttribute(flash_kernel, cudaFuncAttributeMaxDynamicSharedMemorySize, smem_bytes);

    qkv_kernel<<<dim3(SEQ / 64, 3), 256>>>(x, wq, wk, wv);
    flash_kernel<<<SEQ / BM, 256, smem_bytes>>>(out);
}

// round 6
// speedup vs baseline: 3.3025x; 1.5102x over previous
#include <cuda_runtime.h>
#include <cuda_fp16.h>
#include <math.h>
#include <stdint.h>

#define SEQ  8192
#define DIN  512
#define DOUT 64

#define BM 64                  // Q rows per CTA
#define BN 64                  // keys per tile
#define NT (SEQ / BN)          // 128 tiles
#define WQ 68                  // Q-stage stride (floats)
#define HS 72                  // half-tile stride (halves) -> 144B, conflict-free

// (1/sqrt(64)) * log2(e) folded into Q
#define SCALE2 0.18033688011112042f

// smem layout (bytes)
#define QS_OFF   0                       // 64 x WQ floats = 17408
#define KH_OFF(b) (17408 + (b) * 9216)
#define KL_OFF(b) (35840 + (b) * 9216)
#define VT_OFF(b) (54272 + (b) * 9216)
#define MA_OFF   72704                   // 192 floats
#define LA_OFF   73472                   // 192 floats
#define SM_TOTAL 74240

// ---------------- scratch ----------------
__device__ float  g_Q[SEQ * DOUT];
__device__ __half g_Kh[SEQ * DOUT];      // fp16 hi part of K  [seq][64]
__device__ __half g_Kl[SEQ * DOUT];      // fp16 lo part of K  [seq][64]
__device__ __half g_VT[DOUT * SEQ];      // fp16 V transposed  [d][seq]

// ---------------- helpers ----------------
__device__ __forceinline__ float ex2(float x) {
    float r;
    asm("ex2.approx.f32 %0, %1;" : "=f"(r) : "f"(x));
    return r;
}
__device__ __forceinline__ void hmma16(float d[4], uint32_t a0, uint32_t a1,
                                       uint32_t a2, uint32_t a3,
                                       uint32_t b0, uint32_t b1) {
    asm volatile(
        "mma.sync.aligned.m16n8k16.row.col.f32.f16.f16.f32 "
        "{%0,%1,%2,%3}, {%4,%5,%6,%7}, {%8,%9}, {%0,%1,%2,%3};"
        : "+f"(d[0]), "+f"(d[1]), "+f"(d[2]), "+f"(d[3])
        : "r"(a0), "r"(a1), "r"(a2), "r"(a3), "r"(b0), "r"(b1));
}
__device__ __forceinline__ void cp16(void* dst, const void* src) {
    uint32_t d = (uint32_t)__cvta_generic_to_shared(dst);
    asm volatile("cp.async.cg.shared.global [%0], [%1], 16;" :: "r"(d), "l"(src));
}
#define CP_COMMIT() asm volatile("cp.async.commit_group;" ::: "memory")
#define CP_WAIT(n)  asm volatile("cp.async.wait_group %0;" :: "n"(n) : "memory")

__device__ __forceinline__ void q_split(const float* Qs, int rr, int cc,
                                        uint32_t& h, uint32_t& l) {
    float x0 = Qs[rr * WQ + cc] * SCALE2;
    float x1 = Qs[rr * WQ + cc + 1] * SCALE2;
    __half2 hh = __floats2half2_rn(x0, x1);
    float2 hf = __half22float2(hh);
    __half2 ll = __floats2half2_rn(x0 - hf.x, x1 - hf.y);
    h = *(uint32_t*)&hh;
    l = *(uint32_t*)&ll;
}

// ---------------------------------------------------------------------------
// Kernel 1: QKV projection (fp32 SIMT). grid=(SEQ/64,3), block=256.
// K written pre-split fp16 hi/lo; V written fp16, transposed [d][seq].
// ---------------------------------------------------------------------------
__global__ __launch_bounds__(256, 1)
void qkv_kernel(const float* __restrict__ x,
                const float* __restrict__ wq,
                const float* __restrict__ wk,
                const float* __restrict__ wv)
{
    const int mat   = blockIdx.y;
    const float* Wm = (mat == 0) ? wq : (mat == 1) ? wk : wv;
    const int row0  = blockIdx.x * 64;

    __shared__ float xs[64 * 40];
    __shared__ float ws[32 * 64];

    const int tid = threadIdx.x;
    const int ty  = tid >> 4;
    const int tx  = tid & 15;

    float acc[4][4] = {};

    for (int kc = 0; kc < DIN; kc += 32) {
        #pragma unroll
        for (int it = 0; it < 2; ++it) {
            int f = it * 256 + tid;
            int r = f >> 3, kg = f & 7;
            *(float4*)&xs[r * 40 + kg * 4] = *(const float4*)&x[(row0 + r) * DIN + kc + kg * 4];
        }
        #pragma unroll
        for (int it = 0; it < 2; ++it) {
            int f = it * 256 + tid;
            int k = f >> 4, dg = f & 15;
            *(float4*)&ws[k * 64 + dg * 4] = *(const float4*)&Wm[(kc + k) * DOUT + dg * 4];
        }
        __syncthreads();
        #pragma unroll 8
        for (int k = 0; k < 32; ++k) {
            float4 b = *(float4*)&ws[k * 64 + tx * 4];
            #pragma unroll
            for (int m = 0; m < 4; ++m) {
                float a = xs[(ty + 16 * m) * 40 + k];
                acc[m][0] += a * b.x; acc[m][1] += a * b.y;
                acc[m][2] += a * b.z; acc[m][3] += a * b.w;
            }
        }
        __syncthreads();
    }

    if (mat == 0) {
        #pragma unroll
        for (int m = 0; m < 4; ++m) {
            float4 v = make_float4(acc[m][0], acc[m][1], acc[m][2], acc[m][3]);
            *(float4*)&g_Q[(row0 + ty + 16 * m) * DOUT + tx * 4] = v;
        }
    } else if (mat == 1) {
        #pragma unroll
        for (int m = 0; m < 4; ++m) {
            int row = row0 + ty + 16 * m;
            #pragma unroll
            for (int j = 0; j < 4; j += 2) {
                __half2 h = __floats2half2_rn(acc[m][j], acc[m][j + 1]);
                float2 hf = __half22float2(h);
                __half2 l = __floats2half2_rn(acc[m][j] - hf.x, acc[m][j + 1] - hf.y);
                *(__half2*)&g_Kh[row * DOUT + tx * 4 + j] = h;
                *(__half2*)&g_Kl[row * DOUT + tx * 4 + j] = l;
            }
        }
    } else {
        #pragma unroll
        for (int m = 0; m < 4; ++m) {
            int row = row0 + ty + 16 * m;
            #pragma unroll
            for (int j = 0; j < 4; ++j)
                g_VT[(tx * 4 + j) * SEQ + row] = __float2half_rn(acc[m][j]);
        }
    }
}

// ---------------------------------------------------------------------------
// Kernel 2: flash attention, mma.sync fp16 (hi/lo S), grid=128, block=512.
// Warp (mrow = wid&3, kq = wid>>2): rows mrow*16..+15, keys kq*16..+15.
// Fully warp-local online softmax; 4-way key merge once in epilogue.
// ---------------------------------------------------------------------------
__device__ __forceinline__ void load_tile(char* smb, int t, int b, int tid) {
    __half* kh = (__half*)(smb + KH_OFF(b));
    __half* kl = (__half*)(smb + KL_OFF(b));
    __half* vt = (__half*)(smb + VT_OFF(b));
    const int r  = tid >> 3;          // 0..63
    const int c8 = tid & 7;           // 0..7 (8-half chunks)
    cp16(&kh[r * HS + c8 * 8], &g_Kh[(size_t)(t * 64 + r) * DOUT + c8 * 8]);
    cp16(&kl[r * HS + c8 * 8], &g_Kl[(size_t)(t * 64 + r) * DOUT + c8 * 8]);
    cp16(&vt[r * HS + c8 * 8], &g_VT[(size_t)r * SEQ + t * 64 + c8 * 8]);
}

__global__ __launch_bounds__(512, 1)
void flash_kernel(float* __restrict__ out)
{
    extern __shared__ char smb[];
    float* Qs = (float*)(smb + QS_OFF);
    float* mA = (float*)(smb + MA_OFF);
    float* lA = (float*)(smb + LA_OFF);

    const int tid   = threadIdx.x;
    const int lane  = tid & 31;
    const int wid   = tid >> 5;
    const int mrow  = wid & 3;
    const int kq    = wid >> 2;       // key quarter 0..3
    const int kb    = kq * 16;
    const int lq    = lane >> 2;      // 0..7
    const int lr    = lane & 3;       // 0..3
    const int qrow0 = blockIdx.x * BM;
    const int r0    = mrow * 16 + lq;

    // prefetch tile 0
    load_tile(smb, 0, 0, tid);
    CP_COMMIT();

    // stage Q (fp32)
    #pragma unroll
    for (int i = 0; i < 2; ++i) {
        int idx = i * 512 + tid;          // 0..1023 float4 chunks
        int r = idx >> 4, c4 = idx & 15;
        *(float4*)&Qs[r * WQ + c4 * 4] = *(const float4*)&g_Q[(qrow0 + r) * DOUT + c4 * 4];
    }
    __syncthreads();

    // Q fragments: hi/lo fp16, packed half2 (m16n8k16 A layout)
    uint32_t qh[4][4], ql[4][4];
    #pragma unroll
    for (int kc = 0; kc < 4; ++kc) {
        int c = kc * 16 + 2 * lr;
        q_split(Qs, r0,     c,     qh[kc][0], ql[kc][0]);
        q_split(Qs, r0 + 8, c,     qh[kc][1], ql[kc][1]);
        q_split(Qs, r0,     c + 8, qh[kc][2], ql[kc][2]);
        q_split(Qs, r0 + 8, c + 8, qh[kc][3], ql[kc][3]);
    }

    float m0 = -INFINITY, m1 = -INFINITY, l0 = 0.f, l1 = 0.f;
    float o[8][4];
    #pragma unroll
    for (int i = 0; i < 8; ++i)
        o[i][0] = o[i][1] = o[i][2] = o[i][3] = 0.f;

    #pragma unroll 1
    for (int t = 0; t < NT; ++t) {
        const int b = t & 1;
        const __half* kh = (const __half*)(smb + KH_OFF(b));
        const __half* kl = (const __half*)(smb + KL_OFF(b));
        const __half* vt = (const __half*)(smb + VT_OFF(b));

        CP_WAIT(0);
        __syncthreads();

        if (t + 1 < NT) {
            load_tile(smb, t + 1, b ^ 1, tid);
            CP_COMMIT();
        }

        // ---- S = Q K^T over this warp's 16 keys (3-pass fp16 hi/lo) ----
        float s[2][4];
        #pragma unroll
        for (int nt = 0; nt < 2; ++nt) {
            s[nt][0] = s[nt][1] = s[nt][2] = s[nt][3] = 0.f;
            const int krow = kb + nt * 8 + lq;
            const __half* khp = kh + krow * HS + 2 * lr;
            const __half* klp = kl + krow * HS + 2 * lr;
            #pragma unroll
            for (int kc = 0; kc < 4; ++kc) {
                uint32_t h0 = *(const uint32_t*)(khp + kc * 16);
                uint32_t h1 = *(const uint32_t*)(khp + kc * 16 + 8);
                uint32_t c0 = *(const uint32_t*)(klp + kc * 16);
                uint32_t c1 = *(const uint32_t*)(klp + kc * 16 + 8);
                hmma16(s[nt], qh[kc][0], qh[kc][1], qh[kc][2], qh[kc][3], h0, h1);
                hmma16(s[nt], ql[kc][0], ql[kc][1], ql[kc][2], ql[kc][3], h0, h1);
                hmma16(s[nt], qh[kc][0], qh[kc][1], qh[kc][2], qh[kc][3], c0, c1);
            }
        }

        // ---- warp-local online softmax over these 16 keys ----
        float mx0 = fmaxf(fmaxf(s[0][0], s[0][1]), fmaxf(s[1][0], s[1][1]));
        float mx1 = fmaxf(fmaxf(s[0][2], s[0][3]), fmaxf(s[1][2], s[1][3]));
        mx0 = fmaxf(mx0, __shfl_xor_sync(0xffffffffu, mx0, 1));
        mx0 = fmaxf(mx0, __shfl_xor_sync(0xffffffffu, mx0, 2));
        mx1 = fmaxf(mx1, __shfl_xor_sync(0xffffffffu, mx1, 1));
        mx1 = fmaxf(mx1, __shfl_xor_sync(0xffffffffu, mx1, 2));

        float nm0 = fmaxf(m0, mx0), nm1 = fmaxf(m1, mx1);
        float cr0 = ex2(m0 - nm0),  cr1 = ex2(m1 - nm1);
        m0 = nm0; m1 = nm1;

        float p00 = ex2(s[0][0] - nm0), p01 = ex2(s[0][1] - nm0);
        float p02 = ex2(s[0][2] - nm1), p03 = ex2(s[0][3] - nm1);
        float p10 = ex2(s[1][0] - nm0), p11 = ex2(s[1][1] - nm0);
        float p12 = ex2(s[1][2] - nm1), p13 = ex2(s[1][3] - nm1);

        __half2 A0 = __floats2half2_rn(p00, p01);   // (row lq,   k 2lr,2lr+1)
        __half2 A1 = __floats2half2_rn(p02, p03);   // (row lq+8, k 2lr,2lr+1)
        __half2 A2 = __floats2half2_rn(p10, p11);   // (row lq,   k 8+2lr,..)
        __half2 A3 = __floats2half2_rn(p12, p13);   // (row lq+8, k 8+2lr,..)
        float2 f0 = __half22float2(A0), f1 = __half22float2(A1);
        float2 f2 = __half22float2(A2), f3 = __half22float2(A3);

        float ps0 = f0.x + f0.y + f2.x + f2.y;
        float ps1 = f1.x + f1.y + f3.x + f3.y;
        ps0 += __shfl_xor_sync(0xffffffffu, ps0, 1);
        ps0 += __shfl_xor_sync(0xffffffffu, ps0, 2);
        ps1 += __shfl_xor_sync(0xffffffffu, ps1, 1);
        ps1 += __shfl_xor_sync(0xffffffffu, ps1, 2);
        l0 = l0 * cr0 + ps0;
        l1 = l1 * cr1 + ps1;

        #pragma unroll
        for (int nd = 0; nd < 8; ++nd) {
            o[nd][0] *= cr0; o[nd][1] *= cr0;
            o[nd][2] *= cr1; o[nd][3] *= cr1;
        }

        // ---- O_partial += P @ V over these 16 keys (1 k16 chunk) ----
        const uint32_t a0 = *(uint32_t*)&A0, a1 = *(uint32_t*)&A1;
        const uint32_t a2 = *(uint32_t*)&A2, a3 = *(uint32_t*)&A3;
        #pragma unroll
        for (int nd = 0; nd < 8; ++nd) {
            const __half* vp = vt + (nd * 8 + lq) * HS + kb + 2 * lr;
            uint32_t b0 = *(const uint32_t*)vp;
            uint32_t b1 = *(const uint32_t*)(vp + 8);
            hmma16(o[nd], a0, a1, a2, a3, b0, b1);
        }
    }

    // ---- epilogue: merge the 4 key-quarters, normalize, store ----
    __syncthreads();   // all warps done with tile buffers
    // O exchange regions (fp32, stride 64): Qstage / Kh0+Kh1 / Kl0+Kl1
    float* R1 = (float*)(smb + QS_OFF);
    float* R2 = (float*)(smb + KH_OFF(0));
    float* R3 = (float*)(smb + KL_OFF(0));
    float* Rs[3] = { R1, R2, R3 };

    if (kq > 0) {
        float* Rb = Rs[kq - 1];
        if (lr == 0) {
            mA[(kq - 1) * 64 + r0]     = m0;  mA[(kq - 1) * 64 + r0 + 8] = m1;
            lA[(kq - 1) * 64 + r0]     = l0;  lA[(kq - 1) * 64 + r0 + 8] = l1;
        }
        #pragma unroll
        for (int nd = 0; nd < 8; ++nd) {
            *(float2*)&Rb[r0 * 64 + nd * 8 + 2 * lr]       = make_float2(o[nd][0], o[nd][1]);
            *(float2*)&Rb[(r0 + 8) * 64 + nd * 8 + 2 * lr] = make_float2(o[nd][2], o[nd][3]);
        }
    }
    __syncthreads();
    if (kq == 0) {
        float M0 = m0, M1 = m1;
        #pragma unroll
        for (int i = 0; i < 3; ++i) {
            M0 = fmaxf(M0, mA[i * 64 + r0]);
            M1 = fmaxf(M1, mA[i * 64 + r0 + 8]);
        }
        float w0 = ex2(m0 - M0), w1 = ex2(m1 - M1);
        float L0 = l0 * w0, L1 = l1 * w1;
        float acc0[8][2], acc1[8][2];
        #pragma unroll
        for (int nd = 0; nd < 8; ++nd) {
            acc0[nd][0] = o[nd][0] * w0; acc0[nd][1] = o[nd][1] * w0;
            acc1[nd][0] = o[nd][2] * w1; acc1[nd][1] = o[nd][3] * w1;
        }
        #pragma unroll
        for (int i = 0; i < 3; ++i) {
            float u0 = ex2(mA[i * 64 + r0]     - M0);
            float u1 = ex2(mA[i * 64 + r0 + 8] - M1);
            L0 += lA[i * 64 + r0]     * u0;
            L1 += lA[i * 64 + r0 + 8] * u1;
            const float* Rb = Rs[i];
            #pragma unroll
            for (int nd = 0; nd < 8; ++nd) {
                float2 p0 = *(const float2*)&Rb[r0 * 64 + nd * 8 + 2 * lr];
                float2 p1 = *(const float2*)&Rb[(r0 + 8) * 64 + nd * 8 + 2 * lr];
                acc0[nd][0] += p0.x * u0; acc0[nd][1] += p0.y * u0;
                acc1[nd][0] += p1.x * u1; acc1[nd][1] += p1.y * u1;
            }
        }
        float il0 = 1.0f / L0, il1 = 1.0f / L1;
        int row = qrow0 + r0;
        #pragma unroll
        for (int nd = 0; nd < 8; ++nd) {
            *(float2*)&out[row * DOUT + nd * 8 + 2 * lr] =
                make_float2(acc0[nd][0] * il0, acc0[nd][1] * il0);
            *(float2*)&out[(row + 8) * DOUT + nd * 8 + 2 * lr] =
                make_float2(acc1[nd][0] * il1, acc1[nd][1] * il1);
        }
    }
}

// ---------------------------------------------------------------------------
extern "C" void kernel_launch(void* const* d_in, const int* in_sizes, int n_in,
                              void* d_out, int out_size)
{
    (void)in_sizes; (void)n_in; (void)out_size;
    const float* x  = (const float*)d_in[0];
    const float* wq = (const float*)d_in[1];
    const float* wk = (const float*)d_in[2];
    const float* wv = (const float*)d_in[3];
    float* out      = (float*)d_out;

    cudaFuncSetAttribute(flash_kernel, cudaFuncAttributeMaxDynamicSharedMemorySize, SM_TOTAL);

    qkv_kernel<<<dim3(SEQ / 64, 3), 256>>>(x, wq, wk, wv);
    flash_kernel<<<SEQ / BM, 512, SM_TOTAL>>>(out);
}

// round 7
// speedup vs baseline: 3.7668x; 1.1406x over previous
#include <cuda_runtime.h>
#include <cuda_fp16.h>
#include <math.h>
#include <stdint.h>

#define SEQ  8192
#define DIN  512
#define DOUT 64

#define BM 64                  // Q rows per CTA (flash)
#define BN 64                  // keys per tile
#define NT (SEQ / BN)          // 128 tiles
#define WQ 68                  // Q-stage stride (floats)
#define HS 72                  // half-tile stride (halves) -> 144B, conflict-free

// (1/sqrt(64)) * log2(e) folded into Q
#define SCALE2 0.18033688011112042f

// flash smem layout (bytes)
#define QS_OFF   0                       // 64 x WQ floats = 17408
#define KH_OFF(b) (17408 + (b) * 9216)
#define KL_OFF(b) (35840 + (b) * 9216)
#define VT_OFF(b) (54272 + (b) * 9216)
#define MA_OFF   72704                   // 192 floats
#define LA_OFF   73472                   // 192 floats
#define SM_TOTAL 74240

// proj smem layout (bytes): xh[2] xl[2] wh[2] wl[2], each 64x72 halves
#define PX_H(b)  ((b) * 9216)
#define PX_L(b)  (18432 + (b) * 9216)
#define PW_H(b)  (36864 + (b) * 9216)
#define PW_L(b)  (55296 + (b) * 9216)
#define PSM_TOTAL 73728

// ---------------- scratch ----------------
__device__ float  g_Q[SEQ * DOUT];
__device__ __half g_Kh[SEQ * DOUT];      // fp16 hi part of K  [seq][64]
__device__ __half g_Kl[SEQ * DOUT];      // fp16 lo part of K  [seq][64]
__device__ __half g_VT[DOUT * SEQ];      // fp16 V transposed  [d][seq]
__device__ __half g_xh[SEQ * DIN];       // fp16 hi of x
__device__ __half g_xl[SEQ * DIN];       // fp16 lo of x
__device__ __half g_WTh[3 * DOUT * DIN]; // fp16 hi of W^T [mat][n][k]
__device__ __half g_WTl[3 * DOUT * DIN]; // fp16 lo of W^T

// ---------------- helpers ----------------
__device__ __forceinline__ float ex2(float x) {
    float r;
    asm("ex2.approx.f32 %0, %1;" : "=f"(r) : "f"(x));
    return r;
}
__device__ __forceinline__ void hmma16(float d[4], uint32_t a0, uint32_t a1,
                                       uint32_t a2, uint32_t a3,
                                       uint32_t b0, uint32_t b1) {
    asm volatile(
        "mma.sync.aligned.m16n8k16.row.col.f32.f16.f16.f32 "
        "{%0,%1,%2,%3}, {%4,%5,%6,%7}, {%8,%9}, {%0,%1,%2,%3};"
        : "+f"(d[0]), "+f"(d[1]), "+f"(d[2]), "+f"(d[3])
        : "r"(a0), "r"(a1), "r"(a2), "r"(a3), "r"(b0), "r"(b1));
}
__device__ __forceinline__ void cp16(void* dst, const void* src) {
    uint32_t d = (uint32_t)__cvta_generic_to_shared(dst);
    asm volatile("cp.async.cg.shared.global [%0], [%1], 16;" :: "r"(d), "l"(src));
}
#define CP_COMMIT() asm volatile("cp.async.commit_group;" ::: "memory")
#define CP_WAIT(n)  asm volatile("cp.async.wait_group %0;" :: "n"(n) : "memory")

__device__ __forceinline__ void q_split(const float* Qs, int rr, int cc,
                                        uint32_t& h, uint32_t& l) {
    float x0 = Qs[rr * WQ + cc] * SCALE2;
    float x1 = Qs[rr * WQ + cc + 1] * SCALE2;
    __half2 hh = __floats2half2_rn(x0, x1);
    float2 hf = __half22float2(hh);
    __half2 ll = __floats2half2_rn(x0 - hf.x, x1 - hf.y);
    h = *(uint32_t*)&hh;
    l = *(uint32_t*)&ll;
}

// ---------------------------------------------------------------------------
// Kernel 0: convert x -> (xh, xl) fp16; W -> W^T (hi, lo) fp16.
// grid = 4096 (x, float4 per thread) + 384 (W, scalar per thread).
// ---------------------------------------------------------------------------
__global__ __launch_bounds__(256)
void conv_kernel(const float* __restrict__ x,
                 const float* __restrict__ wq,
                 const float* __restrict__ wk,
                 const float* __restrict__ wv)
{
    int bid = blockIdx.x;
    if (bid < 4096) {
        int i = bid * 256 + threadIdx.x;          // float4 index
        float4 v = ((const float4*)x)[i];
        __half2 h0 = __floats2half2_rn(v.x, v.y);
        __half2 h1 = __floats2half2_rn(v.z, v.w);
        float2 f0 = __half22float2(h0), f1 = __half22float2(h1);
        __half2 l0 = __floats2half2_rn(v.x - f0.x, v.y - f0.y);
        __half2 l1 = __floats2half2_rn(v.z - f1.x, v.w - f1.y);
        ((__half2*)g_xh)[2 * i]     = h0;
        ((__half2*)g_xh)[2 * i + 1] = h1;
        ((__half2*)g_xl)[2 * i]     = l0;
        ((__half2*)g_xl)[2 * i + 1] = l1;
    } else {
        int i = (bid - 4096) * 256 + threadIdx.x; // 0..98303
        int mat = i >> 15;
        int rem = i & 32767;
        int k = rem >> 6, n = rem & 63;
        const float* Wm = (mat == 0) ? wq : (mat == 1) ? wk : wv;
        float v = Wm[k * DOUT + n];
        __half h = __float2half_rn(v);
        __half l = __float2half_rn(v - __half2float(h));
        g_WTh[(mat * DOUT + n) * DIN + k] = h;
        g_WTl[(mat * DOUT + n) * DIN + k] = l;
    }
}

// ---------------------------------------------------------------------------
// Kernel 1: QKV projection, fp16 3-pass HMMA. grid=(128,3), block=256.
// 64 rows/CTA x 64 cols, K-chunks of 64, double-buffered.
// Warp: mrow = wid&3 (rows mrow*16..+15), nhalf = wid>>2 (cols nhalf*32..+31).
// ---------------------------------------------------------------------------
__device__ __forceinline__ void proj_load(char* smb, int row0, int mat,
                                          int kc0, int b, int tid) {
    __half* xh = (__half*)(smb + PX_H(b));
    __half* xl = (__half*)(smb + PX_L(b));
    __half* wh = (__half*)(smb + PW_H(b));
    __half* wl = (__half*)(smb + PW_L(b));
    const __half* wthg = g_WTh + (size_t)mat * DOUT * DIN;
    const __half* wtlg = g_WTl + (size_t)mat * DOUT * DIN;
    #pragma unroll
    for (int it = 0; it < 2; ++it) {
        int idx = it * 256 + tid;         // 0..511
        int r = idx >> 3, c8 = idx & 7;
        cp16(&xh[r * HS + c8 * 8], &g_xh[(size_t)(row0 + r) * DIN + kc0 + c8 * 8]);
        cp16(&xl[r * HS + c8 * 8], &g_xl[(size_t)(row0 + r) * DIN + kc0 + c8 * 8]);
        cp16(&wh[r * HS + c8 * 8], &wthg[(size_t)r * DIN + kc0 + c8 * 8]);
        cp16(&wl[r * HS + c8 * 8], &wtlg[(size_t)r * DIN + kc0 + c8 * 8]);
    }
}

__global__ __launch_bounds__(256)
void proj_kernel()
{
    extern __shared__ char smb[];
    const int tid   = threadIdx.x;
    const int lane  = tid & 31;
    const int wid   = tid >> 5;
    const int mrow  = wid & 3;
    const int nhalf = wid >> 2;
    const int lq    = lane >> 2;
    const int lr    = lane & 3;
    const int row0  = blockIdx.x * 64;
    const int mat   = blockIdx.y;
    const int r0    = mrow * 16 + lq;

    proj_load(smb, row0, mat, 0, 0, tid);
    CP_COMMIT();

    float acc[4][4] = {};

    #pragma unroll 1
    for (int c = 0; c < DIN / 64; ++c) {
        const int b = c & 1;
        CP_WAIT(0);
        __syncthreads();
        if (c + 1 < DIN / 64) {
            proj_load(smb, row0, mat, (c + 1) * 64, b ^ 1, tid);
            CP_COMMIT();
        }

        const __half* xh = (const __half*)(smb + PX_H(b));
        const __half* xl = (const __half*)(smb + PX_L(b));
        const __half* wh = (const __half*)(smb + PW_H(b));
        const __half* wl = (const __half*)(smb + PW_L(b));

        // A fragments for this chunk (4 k16 steps, hi/lo)
        uint32_t ah[4][4], al[4][4];
        #pragma unroll
        for (int kc = 0; kc < 4; ++kc) {
            const __half* p0 = xh + r0 * HS + kc * 16 + 2 * lr;
            const __half* p1 = xh + (r0 + 8) * HS + kc * 16 + 2 * lr;
            ah[kc][0] = *(const uint32_t*)p0;
            ah[kc][1] = *(const uint32_t*)p1;
            ah[kc][2] = *(const uint32_t*)(p0 + 8);
            ah[kc][3] = *(const uint32_t*)(p1 + 8);
            const __half* q0 = xl + r0 * HS + kc * 16 + 2 * lr;
            const __half* q1 = xl + (r0 + 8) * HS + kc * 16 + 2 * lr;
            al[kc][0] = *(const uint32_t*)q0;
            al[kc][1] = *(const uint32_t*)q1;
            al[kc][2] = *(const uint32_t*)(q0 + 8);
            al[kc][3] = *(const uint32_t*)(q1 + 8);
        }

        #pragma unroll
        for (int nt = 0; nt < 4; ++nt) {
            const int n = nhalf * 32 + nt * 8 + lq;
            #pragma unroll
            for (int kc = 0; kc < 4; ++kc) {
                const __half* bh = wh + n * HS + kc * 16 + 2 * lr;
                const __half* bl = wl + n * HS + kc * 16 + 2 * lr;
                uint32_t bh0 = *(const uint32_t*)bh;
                uint32_t bh1 = *(const uint32_t*)(bh + 8);
                uint32_t bl0 = *(const uint32_t*)bl;
                uint32_t bl1 = *(const uint32_t*)(bl + 8);
                hmma16(acc[nt], ah[kc][0], ah[kc][1], ah[kc][2], ah[kc][3], bh0, bh1);
                hmma16(acc[nt], al[kc][0], al[kc][1], al[kc][2], al[kc][3], bh0, bh1);
                hmma16(acc[nt], ah[kc][0], ah[kc][1], ah[kc][2], ah[kc][3], bl0, bl1);
            }
        }
    }

    // epilogue
    const int rg = row0 + r0;
    if (mat == 0) {
        #pragma unroll
        for (int nt = 0; nt < 4; ++nt) {
            int cc = nhalf * 32 + nt * 8 + 2 * lr;
            *(float2*)&g_Q[(size_t)rg * DOUT + cc]       = make_float2(acc[nt][0], acc[nt][1]);
            *(float2*)&g_Q[(size_t)(rg + 8) * DOUT + cc] = make_float2(acc[nt][2], acc[nt][3]);
        }
    } else if (mat == 1) {
        #pragma unroll
        for (int nt = 0; nt < 4; ++nt) {
            int cc = nhalf * 32 + nt * 8 + 2 * lr;
            __half2 h0 = __floats2half2_rn(acc[nt][0], acc[nt][1]);
            float2 f0 = __half22float2(h0);
            __half2 l0 = __floats2half2_rn(acc[nt][0] - f0.x, acc[nt][1] - f0.y);
            __half2 h1 = __floats2half2_rn(acc[nt][2], acc[nt][3]);
            float2 f1 = __half22float2(h1);
            __half2 l1 = __floats2half2_rn(acc[nt][2] - f1.x, acc[nt][3] - f1.y);
            *(__half2*)&g_Kh[(size_t)rg * DOUT + cc]       = h0;
            *(__half2*)&g_Kl[(size_t)rg * DOUT + cc]       = l0;
            *(__half2*)&g_Kh[(size_t)(rg + 8) * DOUT + cc] = h1;
            *(__half2*)&g_Kl[(size_t)(rg + 8) * DOUT + cc] = l1;
        }
    } else {
        #pragma unroll
        for (int nt = 0; nt < 4; ++nt) {
            int cc = nhalf * 32 + nt * 8 + 2 * lr;
            g_VT[(size_t)cc * SEQ + rg]           = __float2half_rn(acc[nt][0]);
            g_VT[(size_t)(cc + 1) * SEQ + rg]     = __float2half_rn(acc[nt][1]);
            g_VT[(size_t)cc * SEQ + rg + 8]       = __float2half_rn(acc[nt][2]);
            g_VT[(size_t)(cc + 1) * SEQ + rg + 8] = __float2half_rn(acc[nt][3]);
        }
    }
}

// ---------------------------------------------------------------------------
// Kernel 2: flash attention, mma.sync fp16 (hi/lo S), grid=128, block=512.
// Warp (mrow = wid&3, kq = wid>>2): rows mrow*16..+15, keys kq*16..+15.
// Fully warp-local online softmax; 4-way key merge once in epilogue.
// ---------------------------------------------------------------------------
__device__ __forceinline__ void load_tile(char* smb, int t, int b, int tid) {
    __half* kh = (__half*)(smb + KH_OFF(b));
    __half* kl = (__half*)(smb + KL_OFF(b));
    __half* vt = (__half*)(smb + VT_OFF(b));
    const int r  = tid >> 3;          // 0..63
    const int c8 = tid & 7;           // 0..7 (8-half chunks)
    cp16(&kh[r * HS + c8 * 8], &g_Kh[(size_t)(t * 64 + r) * DOUT + c8 * 8]);
    cp16(&kl[r * HS + c8 * 8], &g_Kl[(size_t)(t * 64 + r) * DOUT + c8 * 8]);
    cp16(&vt[r * HS + c8 * 8], &g_VT[(size_t)r * SEQ + t * 64 + c8 * 8]);
}

__global__ __launch_bounds__(512, 1)
void flash_kernel(float* __restrict__ out)
{
    extern __shared__ char smb[];
    float* Qs = (float*)(smb + QS_OFF);
    float* mA = (float*)(smb + MA_OFF);
    float* lA = (float*)(smb + LA_OFF);

    const int tid   = threadIdx.x;
    const int lane  = tid & 31;
    const int wid   = tid >> 5;
    const int mrow  = wid & 3;
    const int kq    = wid >> 2;       // key quarter 0..3
    const int kb    = kq * 16;
    const int lq    = lane >> 2;      // 0..7
    const int lr    = lane & 3;       // 0..3
    const int qrow0 = blockIdx.x * BM;
    const int r0    = mrow * 16 + lq;

    // prefetch tile 0
    load_tile(smb, 0, 0, tid);
    CP_COMMIT();

    // stage Q (fp32)
    #pragma unroll
    for (int i = 0; i < 2; ++i) {
        int idx = i * 512 + tid;          // 0..1023 float4 chunks
        int r = idx >> 4, c4 = idx & 15;
        *(float4*)&Qs[r * WQ + c4 * 4] = *(const float4*)&g_Q[(qrow0 + r) * DOUT + c4 * 4];
    }
    __syncthreads();

    // Q fragments: hi/lo fp16, packed half2 (m16n8k16 A layout)
    uint32_t qh[4][4], ql[4][4];
    #pragma unroll
    for (int kc = 0; kc < 4; ++kc) {
        int c = kc * 16 + 2 * lr;
        q_split(Qs, r0,     c,     qh[kc][0], ql[kc][0]);
        q_split(Qs, r0 + 8, c,     qh[kc][1], ql[kc][1]);
        q_split(Qs, r0,     c + 8, qh[kc][2], ql[kc][2]);
        q_split(Qs, r0 + 8, c + 8, qh[kc][3], ql[kc][3]);
    }

    float m0 = -INFINITY, m1 = -INFINITY, l0 = 0.f, l1 = 0.f;
    float o[8][4];
    #pragma unroll
    for (int i = 0; i < 8; ++i)
        o[i][0] = o[i][1] = o[i][2] = o[i][3] = 0.f;

    #pragma unroll 1
    for (int t = 0; t < NT; ++t) {
        const int b = t & 1;
        const __half* kh = (const __half*)(smb + KH_OFF(b));
        const __half* kl = (const __half*)(smb + KL_OFF(b));
        const __half* vt = (const __half*)(smb + VT_OFF(b));

        CP_WAIT(0);
        __syncthreads();

        if (t + 1 < NT) {
            load_tile(smb, t + 1, b ^ 1, tid);
            CP_COMMIT();
        }

        // ---- S = Q K^T over this warp's 16 keys (3-pass fp16 hi/lo) ----
        float s[2][4];
        #pragma unroll
        for (int nt = 0; nt < 2; ++nt) {
            s[nt][0] = s[nt][1] = s[nt][2] = s[nt][3] = 0.f;
            const int krow = kb + nt * 8 + lq;
            const __half* khp = kh + krow * HS + 2 * lr;
            const __half* klp = kl + krow * HS + 2 * lr;
            #pragma unroll
            for (int kc = 0; kc < 4; ++kc) {
                uint32_t h0 = *(const uint32_t*)(khp + kc * 16);
                uint32_t h1 = *(const uint32_t*)(khp + kc * 16 + 8);
                uint32_t c0 = *(const uint32_t*)(klp + kc * 16);
                uint32_t c1 = *(const uint32_t*)(klp + kc * 16 + 8);
                hmma16(s[nt], qh[kc][0], qh[kc][1], qh[kc][2], qh[kc][3], h0, h1);
                hmma16(s[nt], ql[kc][0], ql[kc][1], ql[kc][2], ql[kc][3], h0, h1);
                hmma16(s[nt], qh[kc][0], qh[kc][1], qh[kc][2], qh[kc][3], c0, c1);
            }
        }

        // ---- warp-local online softmax over these 16 keys ----
        float mx0 = fmaxf(fmaxf(s[0][0], s[0][1]), fmaxf(s[1][0], s[1][1]));
        float mx1 = fmaxf(fmaxf(s[0][2], s[0][3]), fmaxf(s[1][2], s[1][3]));
        mx0 = fmaxf(mx0, __shfl_xor_sync(0xffffffffu, mx0, 1));
        mx0 = fmaxf(mx0, __shfl_xor_sync(0xffffffffu, mx0, 2));
        mx1 = fmaxf(mx1, __shfl_xor_sync(0xffffffffu, mx1, 1));
        mx1 = fmaxf(mx1, __shfl_xor_sync(0xffffffffu, mx1, 2));

        float nm0 = fmaxf(m0, mx0), nm1 = fmaxf(m1, mx1);
        float cr0 = ex2(m0 - nm0),  cr1 = ex2(m1 - nm1);
        m0 = nm0; m1 = nm1;

        float p00 = ex2(s[0][0] - nm0), p01 = ex2(s[0][1] - nm0);
        float p02 = ex2(s[0][2] - nm1), p03 = ex2(s[0][3] - nm1);
        float p10 = ex2(s[1][0] - nm0), p11 = ex2(s[1][1] - nm0);
        float p12 = ex2(s[1][2] - nm1), p13 = ex2(s[1][3] - nm1);

        __half2 A0 = __floats2half2_rn(p00, p01);   // (row lq,   k 2lr,2lr+1)
        __half2 A1 = __floats2half2_rn(p02, p03);   // (row lq+8, k 2lr,2lr+1)
        __half2 A2 = __floats2half2_rn(p10, p11);   // (row lq,   k 8+2lr,..)
        __half2 A3 = __floats2half2_rn(p12, p13);   // (row lq+8, k 8+2lr,..)
        float2 f0 = __half22float2(A0), f1 = __half22float2(A1);
        float2 f2 = __half22float2(A2), f3 = __half22float2(A3);

        float ps0 = f0.x + f0.y + f2.x + f2.y;
        float ps1 = f1.x + f1.y + f3.x + f3.y;
        ps0 += __shfl_xor_sync(0xffffffffu, ps0, 1);
        ps0 += __shfl_xor_sync(0xffffffffu, ps0, 2);
        ps1 += __shfl_xor_sync(0xffffffffu, ps1, 1);
        ps1 += __shfl_xor_sync(0xffffffffu, ps1, 2);
        l0 = l0 * cr0 + ps0;
        l1 = l1 * cr1 + ps1;

        // rescale only when some row's max actually moved (warp-uniform)
        if (__any_sync(0xffffffffu,
                       (__float_as_uint(cr0) != 0x3f800000u) |
                       (__float_as_uint(cr1) != 0x3f800000u))) {
            #pragma unroll
            for (int nd = 0; nd < 8; ++nd) {
                o[nd][0] *= cr0; o[nd][1] *= cr0;
                o[nd][2] *= cr1; o[nd][3] *= cr1;
            }
        }

        // ---- O_partial += P @ V over these 16 keys (1 k16 chunk) ----
        const uint32_t a0 = *(uint32_t*)&A0, a1 = *(uint32_t*)&A1;
        const uint32_t a2 = *(uint32_t*)&A2, a3 = *(uint32_t*)&A3;
        #pragma unroll
        for (int nd = 0; nd < 8; ++nd) {
            const __half* vp = vt + (nd * 8 + lq) * HS + kb + 2 * lr;
            uint32_t b0 = *(const uint32_t*)vp;
            uint32_t b1 = *(const uint32_t*)(vp + 8);
            hmma16(o[nd], a0, a1, a2, a3, b0, b1);
        }
    }

    // ---- epilogue: merge the 4 key-quarters, normalize, store ----
    __syncthreads();   // all warps done with tile buffers
    float* R1 = (float*)(smb + QS_OFF);
    float* R2 = (float*)(smb + KH_OFF(0));
    float* R3 = (float*)(smb + KL_OFF(0));
    float* Rs[3] = { R1, R2, R3 };

    if (kq > 0) {
        float* Rb = Rs[kq - 1];
        if (lr == 0) {
            mA[(kq - 1) * 64 + r0]     = m0;  mA[(kq - 1) * 64 + r0 + 8] = m1;
            lA[(kq - 1) * 64 + r0]     = l0;  lA[(kq - 1) * 64 + r0 + 8] = l1;
        }
        #pragma unroll
        for (int nd = 0; nd < 8; ++nd) {
            *(float2*)&Rb[r0 * 64 + nd * 8 + 2 * lr]       = make_float2(o[nd][0], o[nd][1]);
            *(float2*)&Rb[(r0 + 8) * 64 + nd * 8 + 2 * lr] = make_float2(o[nd][2], o[nd][3]);
        }
    }
    __syncthreads();
    if (kq == 0) {
        float M0 = m0, M1 = m1;
        #pragma unroll
        for (int i = 0; i < 3; ++i) {
            M0 = fmaxf(M0, mA[i * 64 + r0]);
            M1 = fmaxf(M1, mA[i * 64 + r0 + 8]);
        }
        float w0 = ex2(m0 - M0), w1 = ex2(m1 - M1);
        float L0 = l0 * w0, L1 = l1 * w1;
        float acc0[8][2], acc1[8][2];
        #pragma unroll
        for (int nd = 0; nd < 8; ++nd) {
            acc0[nd][0] = o[nd][0] * w0; acc0[nd][1] = o[nd][1] * w0;
            acc1[nd][0] = o[nd][2] * w1; acc1[nd][1] = o[nd][3] * w1;
        }
        #pragma unroll
        for (int i = 0; i < 3; ++i) {
            float u0 = ex2(mA[i * 64 + r0]     - M0);
            float u1 = ex2(mA[i * 64 + r0 + 8] - M1);
            L0 += lA[i * 64 + r0]     * u0;
            L1 += lA[i * 64 + r0 + 8] * u1;
            const float* Rb = Rs[i];
            #pragma unroll
            for (int nd = 0; nd < 8; ++nd) {
                float2 p0 = *(const float2*)&Rb[r0 * 64 + nd * 8 + 2 * lr];
                float2 p1 = *(const float2*)&Rb[(r0 + 8) * 64 + nd * 8 + 2 * lr];
                acc0[nd][0] += p0.x * u0; acc0[nd][1] += p0.y * u0;
                acc1[nd][0] += p1.x * u1; acc1[nd][1] += p1.y * u1;
            }
        }
        float il0 = 1.0f / L0, il1 = 1.0f / L1;
        int row = qrow0 + r0;
        #pragma unroll
        for (int nd = 0; nd < 8; ++nd) {
            *(float2*)&out[row * DOUT + nd * 8 + 2 * lr] =
                make_float2(acc0[nd][0] * il0, acc0[nd][1] * il0);
            *(float2*)&out[(row + 8) * DOUT + nd * 8 + 2 * lr] =
                make_float2(acc1[nd][0] * il1, acc1[nd][1] * il1);
        }
    }
}

// ---------------------------------------------------------------------------
extern "C" void kernel_launch(void* const* d_in, const int* in_sizes, int n_in,
                              void* d_out, int out_size)
{
    (void)in_sizes; (void)n_in; (void)out_size;
    const float* x  = (const float*)d_in[0];
    const float* wq = (const float*)d_in[1];
    const float* wk = (const float*)d_in[2];
    const float* wv = (const float*)d_in[3];
    float* out      = (float*)d_out;

    cudaFuncSetAttribute(proj_kernel,  cudaFuncAttributeMaxDynamicSharedMemorySize, PSM_TOTAL);
    cudaFuncSetAttribute(flash_kernel, cudaFuncAttributeMaxDynamicSharedMemorySize, SM_TOTAL);

    conv_kernel<<<4480, 256>>>(x, wq, wk, wv);
    proj_kernel<<<dim3(SEQ / 64, 3), 256, PSM_TOTAL>>>();
    flash_kernel<<<SEQ / BM, 512, SM_TOTAL>>>(out);
}